// round 2
// baseline (speedup 1.0000x reference)
#include <cuda_runtime.h>
#include <cuda_bf16.h>
#include <math.h>

// Problem constants
// B=32, A=32, S=128, D=1024, N*H=1024
// Reduction: logits[b,x] = Q[b,x]·(sum_a K[b,a]) - Q[b,x]·K[b,x]
//   where Q = (cls@Wq + bq)*m, K = (cls@Wk + bk)*m, cls = enc[:, :, 0, :].
// Then softmax(logits + (1-m)*-1e5).

#define BM 128
#define BN 128
#define BK 16
#define TM 8
#define TN 8

// Scratch: [1024 rows][2048 cols]: cols 0..1023 = Q, 1024..2047 = K
__device__ float g_qk[1024 * 2048];

__global__ __launch_bounds__(256) void qk_gemm(
    const float* __restrict__ enc,
    const int*   __restrict__ mask,
    const float* __restrict__ wq,
    const float* __restrict__ bq,
    const float* __restrict__ wk,
    const float* __restrict__ bk)
{
    const int bx = blockIdx.x;   // 0..15 : col tiles (0..7 -> Q/wq, 8..15 -> K/wk)
    const int by = blockIdx.y;   // 0..7  : row tiles
    const bool isQ = (bx < 8);
    const float* __restrict__ W    = isQ ? wq : wk;
    const float* __restrict__ bias = isQ ? bq : bk;
    const int colBase = (bx & 7) * BN;

    __shared__ float As[BK][BM];
    __shared__ float Bs[BK][BN];

    const int tid = threadIdx.x;

    // A tile load mapping: 128 rows x 16 cols = 512 float4, 2 per thread
    const int aRow = tid >> 2;          // 0..63
    const int aCol = (tid & 3) * 4;     // 0,4,8,12
    // B tile load mapping: 16 rows x 128 cols = 512 float4, 2 per thread
    const int bRow = tid >> 5;          // 0..7
    const int bCol = (tid & 31) * 4;    // 0..124

    const int tCol = (tid & 15) * TN;   // 0..120
    const int tRow = (tid >> 4) * TM;   // 0..120

    float acc[TM][TN] = {};
    float regM[TM], regN[TN];

    const size_t encRowStride = (size_t)128 * 1024;  // S*D floats between cls rows
    const float* Aptr = enc + (size_t)(by * BM) * encRowStride;

    for (int k0 = 0; k0 < 1024; k0 += BK) {
        // ---- load A tile (128x16), store transposed As[k][m]
        #pragma unroll
        for (int r = 0; r < BM; r += 64) {
            float4 v = *reinterpret_cast<const float4*>(
                Aptr + (size_t)(aRow + r) * encRowStride + k0 + aCol);
            As[aCol + 0][aRow + r] = v.x;
            As[aCol + 1][aRow + r] = v.y;
            As[aCol + 2][aRow + r] = v.z;
            As[aCol + 3][aRow + r] = v.w;
        }
        // ---- load B tile (16x128)
        #pragma unroll
        for (int r = 0; r < BK; r += 8) {
            *reinterpret_cast<float4*>(&Bs[bRow + r][bCol]) =
                *reinterpret_cast<const float4*>(
                    W + (size_t)(k0 + bRow + r) * 1024 + colBase + bCol);
        }
        __syncthreads();

        #pragma unroll
        for (int k = 0; k < BK; k++) {
            #pragma unroll
            for (int i = 0; i < TM; i += 4) {
                float4 v = *reinterpret_cast<const float4*>(&As[k][tRow + i]);
                regM[i + 0] = v.x; regM[i + 1] = v.y;
                regM[i + 2] = v.z; regM[i + 3] = v.w;
            }
            #pragma unroll
            for (int j = 0; j < TN; j += 4) {
                float4 v = *reinterpret_cast<const float4*>(&Bs[k][tCol + j]);
                regN[j + 0] = v.x; regN[j + 1] = v.y;
                regN[j + 2] = v.z; regN[j + 3] = v.w;
            }
            #pragma unroll
            for (int i = 0; i < TM; i++)
                #pragma unroll
                for (int j = 0; j < TN; j++)
                    acc[i][j] = fmaf(regM[i], regN[j], acc[i][j]);
        }
        __syncthreads();
    }

    // ---- epilogue: add bias, apply doc mask, store to scratch
    const int colOut0 = (isQ ? 0 : 1024) + colBase + tCol;
    #pragma unroll
    for (int i = 0; i < TM; i++) {
        const int row = by * BM + tRow + i;
        const float m = (float)mask[row];   // mask is (32,32) flat = 1024 rows
        float* outp = &g_qk[(size_t)row * 2048 + colOut0];
        #pragma unroll
        for (int j = 0; j < TN; j += 4) {
            float4 v;
            v.x = (acc[i][j + 0] + bias[colBase + tCol + j + 0]) * m;
            v.y = (acc[i][j + 1] + bias[colBase + tCol + j + 1]) * m;
            v.z = (acc[i][j + 2] + bias[colBase + tCol + j + 2]) * m;
            v.w = (acc[i][j + 3] + bias[colBase + tCol + j + 3]) * m;
            *reinterpret_cast<float4*>(outp + j) = v;
        }
    }
}

// One block per batch b: Ksum, the two dot products, softmax.
__global__ __launch_bounds__(256) void doc_epilogue(
    const int* __restrict__ mask,
    float* __restrict__ out)
{
    const int b = blockIdx.x;            // 0..31
    const int tid = threadIdx.x;
    const int warp = tid >> 5;
    const int lane = tid & 31;

    __shared__ float ksum[1024];
    __shared__ float logits[32];

    const float* __restrict__ base = &g_qk[(size_t)b * 32 * 2048];

    // Ksum[d] = sum_a K[b,a,d]  (K rows are already masked)
    for (int d = tid; d < 1024; d += 256) {
        float s = 0.f;
        #pragma unroll
        for (int a = 0; a < 32; a++)
            s += base[(size_t)a * 2048 + 1024 + d];
        ksum[d] = s;
    }
    __syncthreads();

    // logits[x] = Q[x]·ksum - Q[x]·K[x]; warp w handles x in {w, w+8, w+16, w+24}
    #pragma unroll
    for (int xi = 0; xi < 4; xi++) {
        const int x = warp + xi * 8;
        const float* __restrict__ q = base + (size_t)x * 2048;
        const float* __restrict__ k = q + 1024;
        float s = 0.f;
        for (int d = lane; d < 1024; d += 32) {
            float4 qv = *reinterpret_cast<const float4*>(q + 0) ; // placeholder avoid
            (void)qv;
            break;
        }
        // vectorized: lane handles 8 float4 chunks (1024/32/4 = 8)
        s = 0.f;
        for (int c = 0; c < 8; c++) {
            const int d = (lane + c * 32) * 4;
            float4 qv = *reinterpret_cast<const float4*>(q + d);
            float4 kv = *reinterpret_cast<const float4*>(k + d);
            float4 sv = *reinterpret_cast<const float4*>(&ksum[d]);
            s = fmaf(qv.x, sv.x - kv.x, s);
            s = fmaf(qv.y, sv.y - kv.y, s);
            s = fmaf(qv.z, sv.z - kv.z, s);
            s = fmaf(qv.w, sv.w - kv.w, s);
        }
        #pragma unroll
        for (int o = 16; o > 0; o >>= 1)
            s += __shfl_xor_sync(0xFFFFFFFFu, s, o);
        if (lane == 0) {
            const float m = (float)mask[b * 32 + x];
            logits[x] = s + (1.0f - m) * -100000.0f;
        }
    }
    __syncthreads();

    // softmax over the 32 docs (warp 0)
    if (warp == 0) {
        float v = logits[lane];
        float mx = v;
        #pragma unroll
        for (int o = 16; o > 0; o >>= 1)
            mx = fmaxf(mx, __shfl_xor_sync(0xFFFFFFFFu, mx, o));
        float e = expf(v - mx);
        float sum = e;
        #pragma unroll
        for (int o = 16; o > 0; o >>= 1)
            sum += __shfl_xor_sync(0xFFFFFFFFu, sum, o);
        out[b * 32 + lane] = e / sum;
    }
}

extern "C" void kernel_launch(void* const* d_in, const int* in_sizes, int n_in,
                              void* d_out, int out_size) {
    const float* enc  = (const float*)d_in[0];   // (32,32,128,1024) f32
    const int*   mask = (const int*)  d_in[1];   // (32,32) int32
    const float* wq   = (const float*)d_in[2];   // (1024,16,64) f32 = (1024,1024)
    const float* bq   = (const float*)d_in[3];   // (16,64) = 1024
    const float* wk   = (const float*)d_in[4];
    const float* bk   = (const float*)d_in[5];
    float* out = (float*)d_out;                  // (32,32) f32

    dim3 grid(16, 8);
    qk_gemm<<<grid, 256>>>(enc, mask, wq, bq, wk, bk);
    doc_epilogue<<<32, 256>>>(mask, out);
}

// round 4
// speedup vs baseline: 4.3679x; 4.3679x over previous
#include <cuda_runtime.h>
#include <cuda_bf16.h>
#include <cstdint>
#include <math.h>

// ============================================================
// DocAttention on GB300 (sm_103 family-safe: mma.sync bf16).
//   logits[b,x] = Q[b,x]·(Σ_a K[b,a]) − Q[b,x]·K[b,x]
//   Q = (cls@Wq + bq)*m, K = (cls@Wk + bk)*m
//   out = softmax(logits + (1−m)·−1e5)
// GEMM: C[1024 x 2048] = clsBF16[1024x1024] @ [Wq|Wk]^T (bf16, f32 acc)
// ============================================================

__device__ __forceinline__ uint32_t smem_u32(const void* p) {
    uint32_t a;
    asm("{ .reg .u64 t; cvta.to.shared.u64 t, %1; cvt.u32.u64 %0, t; }"
        : "=r"(a) : "l"(p));
    return a;
}

// ---------------- scratch (device globals; no allocation) ----------------
__device__ __align__(16) __nv_bfloat16 g_A[1024 * 1024];    // cls bf16 [m][k]
__device__ __align__(16) __nv_bfloat16 g_B[2048 * 1024];    // [WqT|WkT] bf16 [n][k]
__device__ float g_qk[1024 * 2048];                          // Q | K (masked, +bias)

// ---------------- convert cls rows to bf16 ----------------
__global__ __launch_bounds__(256) void convert_cls(const float* __restrict__ enc) {
    const int row = blockIdx.x;          // 0..1023
    const int t = threadIdx.x;           // float4 index within row
    const float4 v = reinterpret_cast<const float4*>(enc + (size_t)row * 131072)[t];
    __nv_bfloat16 h[4];
    h[0] = __float2bfloat16(v.x);
    h[1] = __float2bfloat16(v.y);
    h[2] = __float2bfloat16(v.z);
    h[3] = __float2bfloat16(v.w);
    *reinterpret_cast<uint2*>(g_A + (size_t)row * 1024 + t * 4) =
        *reinterpret_cast<uint2*>(h);
}

// ---------------- transpose W[d][n] -> B[n][d] bf16 ----------------
__global__ __launch_bounds__(256) void convert_w(const float* __restrict__ wq,
                                                 const float* __restrict__ wk) {
    __shared__ float tile[32][33];
    const float* __restrict__ W = blockIdx.z ? wk : wq;
    const int tx = threadIdx.x, ty = threadIdx.y;       // 32 x 8
    const int n = blockIdx.x * 32 + tx;
    const int k0 = blockIdx.y * 32;
    #pragma unroll
    for (int i = 0; i < 4; i++)
        tile[ty + i * 8][tx] = W[(size_t)(k0 + ty + i * 8) * 1024 + n];
    __syncthreads();
    const int k = k0 + tx;
    const int nb = blockIdx.x * 32;
    #pragma unroll
    for (int i = 0; i < 4; i++) {
        const int nrow = nb + ty + i * 8;
        g_B[(size_t)(blockIdx.z * 1024 + nrow) * 1024 + k] =
            __float2bfloat16(tile[tx][ty + i * 8]);
    }
}

// ---------------- mma.sync GEMM ----------------
// CTA: 128x128 tile, 256 threads = 8 warps in 2(M) x 4(N); warp tile 64x32.
// K pipeline: BK=64 per stage, 3 stages, cp.async.
#define BK 64
#define STAGE_BYTES 32768   // (128 rows A + 128 rows B) * 128 bytes
#define NSTAGE 3

__global__ __launch_bounds__(256, 1)
void qk_mma_sync(const int* __restrict__ mask,
                 const float* __restrict__ bq,
                 const float* __restrict__ bk) {
    extern __shared__ __align__(1024) char smem[];
    const uint32_t base = smem_u32(smem);
    const int tid = threadIdx.x;
    const int warp = tid >> 5, lane = tid & 31;
    const int mBase = blockIdx.y * 128;
    const int nBase = blockIdx.x * 128;
    const int mw = (warp & 1) * 64;
    const int nw = (warp >> 1) * 32;

    float c[4][4][4];
    #pragma unroll
    for (int i = 0; i < 4; i++)
        #pragma unroll
        for (int j = 0; j < 4; j++)
            #pragma unroll
            for (int r = 0; r < 4; r++) c[i][j][r] = 0.f;

    // -------- producer: one K-chunk into stage kb%3 --------
    auto issue = [&](int kb) {
        const int stage = kb % NSTAGE;
        const uint32_t sA = base + (uint32_t)stage * STAGE_BYTES;
        const uint32_t sB = sA + 16384;
        const int k0 = kb * BK;
        #pragma unroll
        for (int i = 0; i < 4; i++) {
            const int idx = i * 256 + tid;          // 0..1023
            const int row = idx >> 3;               // 0..127
            const int ch = idx & 7;                 // 16B chunk in row
            const uint32_t swz = (uint32_t)((ch ^ (row & 7)) << 4);
            const __nv_bfloat16* gA =
                g_A + (size_t)(mBase + row) * 1024 + k0 + ch * 8;
            const __nv_bfloat16* gB =
                g_B + (size_t)(nBase + row) * 1024 + k0 + ch * 8;
            asm volatile("cp.async.cg.shared.global [%0], [%1], 16;"
                         :: "r"(sA + (uint32_t)row * 128 + swz), "l"(gA));
            asm volatile("cp.async.cg.shared.global [%0], [%1], 16;"
                         :: "r"(sB + (uint32_t)row * 128 + swz), "l"(gB));
        }
        asm volatile("cp.async.commit_group;");
    };

    // -------- consumer: compute one stage --------
    const int lj = lane >> 3;       // 0..3 (which 8x8 matrix this lane addresses)
    const int li = lane & 7;        // row within matrix
    auto compute = [&](int stage) {
        const uint32_t sA = base + (uint32_t)stage * STAGE_BYTES;
        const uint32_t sB = sA + 16384;
        #pragma unroll
        for (int kc = 0; kc < BK / 16; kc++) {
            uint32_t a[4][4];
            #pragma unroll
            for (int mt = 0; mt < 4; mt++) {
                const int row = mw + mt * 16 + ((lj & 1) << 3) + li;
                const int ch = kc * 2 + (lj >> 1);
                const uint32_t addr =
                    sA + (uint32_t)row * 128 + (uint32_t)((ch ^ (row & 7)) << 4);
                asm volatile("ldmatrix.sync.aligned.m8n8.x4.shared.b16 "
                             "{%0,%1,%2,%3}, [%4];"
                             : "=r"(a[mt][0]), "=r"(a[mt][1]),
                               "=r"(a[mt][2]), "=r"(a[mt][3])
                             : "r"(addr));
            }
            uint32_t b[2][4];
            #pragma unroll
            for (int nh = 0; nh < 2; nh++) {
                const int row = nw + nh * 16 + ((lj >> 1) << 3) + li;
                const int ch = kc * 2 + (lj & 1);
                const uint32_t addr =
                    sB + (uint32_t)row * 128 + (uint32_t)((ch ^ (row & 7)) << 4);
                asm volatile("ldmatrix.sync.aligned.m8n8.x4.shared.b16 "
                             "{%0,%1,%2,%3}, [%4];"
                             : "=r"(b[nh][0]), "=r"(b[nh][1]),
                               "=r"(b[nh][2]), "=r"(b[nh][3])
                             : "r"(addr));
            }
            #pragma unroll
            for (int mt = 0; mt < 4; mt++)
                #pragma unroll
                for (int nt = 0; nt < 4; nt++) {
                    const uint32_t b0 = b[nt >> 1][(nt & 1) * 2 + 0];
                    const uint32_t b1 = b[nt >> 1][(nt & 1) * 2 + 1];
                    asm volatile(
                        "mma.sync.aligned.m16n8k16.row.col.f32.bf16.bf16.f32 "
                        "{%0,%1,%2,%3}, {%4,%5,%6,%7}, {%8,%9}, {%0,%1,%2,%3};"
                        : "+f"(c[mt][nt][0]), "+f"(c[mt][nt][1]),
                          "+f"(c[mt][nt][2]), "+f"(c[mt][nt][3])
                        : "r"(a[mt][0]), "r"(a[mt][1]),
                          "r"(a[mt][2]), "r"(a[mt][3]),
                          "r"(b0), "r"(b1));
                }
        }
    };

    // -------- pipeline --------
    issue(0); issue(1); issue(2);
    for (int kb = 0; kb < 16; kb++) {
        if (kb <= 13)      asm volatile("cp.async.wait_group 2;");
        else if (kb == 14) asm volatile("cp.async.wait_group 1;");
        else               asm volatile("cp.async.wait_group 0;");
        __syncthreads();
        compute(kb % NSTAGE);
        __syncthreads();
        if (kb + NSTAGE < 16) issue(kb + NSTAGE);
    }

    // -------- epilogue: bias + mask -> g_qk (f32) --------
    #pragma unroll
    for (int mt = 0; mt < 4; mt++) {
        #pragma unroll
        for (int half = 0; half < 2; half++) {
            const int row = mBase + mw + mt * 16 + (lane >> 2) + half * 8;
            const float m = (float)mask[row];
            #pragma unroll
            for (int nt = 0; nt < 4; nt++) {
                const int col = nBase + nw + nt * 8 + (lane & 3) * 2;
                const float bias0 = (col < 1024) ? bq[col] : bk[col - 1024];
                const float bias1 = (col + 1 < 1024) ? bq[col + 1] : bk[col + 1 - 1024];
                float2 v;
                v.x = (c[mt][nt][half * 2 + 0] + bias0) * m;
                v.y = (c[mt][nt][half * 2 + 1] + bias1) * m;
                *reinterpret_cast<float2*>(g_qk + (size_t)row * 2048 + col) = v;
            }
        }
    }
}

// ---------------- per-batch reduction + softmax ----------------
__global__ __launch_bounds__(1024) void doc_epilogue(const int* __restrict__ mask,
                                                     float* __restrict__ out) {
    const int b = blockIdx.x;
    const int tid = threadIdx.x, warp = tid >> 5, lane = tid & 31;
    __shared__ float ks[1024];
    __shared__ float lg[32];

    const float* __restrict__ base = g_qk + (size_t)b * 32 * 2048;

    // ksum[d] = sum_a K[b,a,d] (K already masked)
    float s = 0.f;
    #pragma unroll
    for (int a = 0; a < 32; a++) s += base[a * 2048 + 1024 + tid];
    ks[tid] = s;
    __syncthreads();

    // warp x: logit[x] = Q[x]·(ksum − K[x])
    {
        const int x = warp;
        const float* __restrict__ q = base + (size_t)x * 2048;
        const float* __restrict__ k = q + 1024;
        float acc = 0.f;
        #pragma unroll
        for (int ci = 0; ci < 8; ci++) {
            const int d = (lane + ci * 32) * 4;
            const float4 qv = *reinterpret_cast<const float4*>(q + d);
            const float4 kv = *reinterpret_cast<const float4*>(k + d);
            const float4 sv = *reinterpret_cast<const float4*>(ks + d);
            acc = fmaf(qv.x, sv.x - kv.x, acc);
            acc = fmaf(qv.y, sv.y - kv.y, acc);
            acc = fmaf(qv.z, sv.z - kv.z, acc);
            acc = fmaf(qv.w, sv.w - kv.w, acc);
        }
        #pragma unroll
        for (int o = 16; o > 0; o >>= 1)
            acc += __shfl_xor_sync(0xFFFFFFFFu, acc, o);
        if (lane == 0) {
            const float m = (float)mask[b * 32 + x];
            lg[x] = acc + (1.0f - m) * -100000.0f;
        }
    }
    __syncthreads();

    if (warp == 0) {
        float v = lg[lane];
        float mx = v;
        #pragma unroll
        for (int o = 16; o > 0; o >>= 1)
            mx = fmaxf(mx, __shfl_xor_sync(0xFFFFFFFFu, mx, o));
        float e = expf(v - mx);
        float sum = e;
        #pragma unroll
        for (int o = 16; o > 0; o >>= 1)
            sum += __shfl_xor_sync(0xFFFFFFFFu, sum, o);
        out[b * 32 + lane] = e / sum;
    }
}

extern "C" void kernel_launch(void* const* d_in, const int* in_sizes, int n_in,
                              void* d_out, int out_size) {
    const float* enc  = (const float*)d_in[0];   // (32,32,128,1024) f32
    const int*   mask = (const int*)  d_in[1];   // (32,32) int32
    const float* wq   = (const float*)d_in[2];   // (1024,16,64) f32
    const float* bq   = (const float*)d_in[3];   // (16,64)
    const float* wk   = (const float*)d_in[4];
    const float* bk   = (const float*)d_in[5];
    float* out = (float*)d_out;                  // (32,32) f32

    static bool attr_set = false;
    if (!attr_set) {
        cudaFuncSetAttribute(qk_mma_sync,
                             cudaFuncAttributeMaxDynamicSharedMemorySize,
                             NSTAGE * STAGE_BYTES);
        attr_set = true;
    }

    convert_cls<<<1024, 256>>>(enc);
    convert_w<<<dim3(32, 32, 2), dim3(32, 8)>>>(wq, wk);
    qk_mma_sync<<<dim3(16, 8), 256, NSTAGE * STAGE_BYTES>>>(mask, bq, bk);
    doc_epilogue<<<32, 1024>>>(mask, out);
}

// round 5
// speedup vs baseline: 4.4011x; 1.0076x over previous
#include <cuda_runtime.h>
#include <cuda_bf16.h>
#include <cstdint>
#include <math.h>

// ============================================================
// DocAttention on GB300 (sm_103 family-safe: mma.sync bf16).
//   logits[b,x] = Q[b,x]·(Σ_a K[b,a]) − Q[b,x]·K[b,x]
//   Q = (cls@Wq + bq)*m, K = (cls@Wk + bk)*m
//   out = softmax(logits + (1−m)·−1e5)
// ============================================================

__device__ __forceinline__ uint32_t smem_u32(const void* p) {
    uint32_t a;
    asm("{ .reg .u64 t; cvta.to.shared.u64 t, %1; cvt.u32.u64 %0, t; }"
        : "=r"(a) : "l"(p));
    return a;
}

// ---------------- scratch (device globals; no allocation) ----------------
__device__ __align__(16) __nv_bfloat16 g_A[1024 * 1024];    // cls bf16 [m][k]
__device__ __align__(16) __nv_bfloat16 g_B[2048 * 1024];    // [WqT|WkT] bf16 [n][k]
__device__ float g_qk[1024 * 2048];                          // Q | K (masked, +bias)
__device__ float g_part[1024 * 8];                           // partial logits [b*32+x][slice]

// ---------------- merged converts ----------------
// blocks [0,1024): cls row -> bf16
// blocks [1024,3072): W transpose+convert
__global__ __launch_bounds__(256) void convert_all(const float* __restrict__ enc,
                                                   const float* __restrict__ wq,
                                                   const float* __restrict__ wk) {
    __shared__ float tile[32][33];
    const int blk = blockIdx.x;
    const int tid = threadIdx.x;

    if (blk < 1024) {
        const int row = blk;
        const float4 v = reinterpret_cast<const float4*>(enc + (size_t)row * 131072)[tid];
        __nv_bfloat16 h[4];
        h[0] = __float2bfloat16(v.x);
        h[1] = __float2bfloat16(v.y);
        h[2] = __float2bfloat16(v.z);
        h[3] = __float2bfloat16(v.w);
        *reinterpret_cast<uint2*>(g_A + (size_t)row * 1024 + tid * 4) =
            *reinterpret_cast<uint2*>(h);
        return;
    }

    const int idx = blk - 1024;              // 0..2047
    const int z = idx >> 10;                 // 0 = wq, 1 = wk
    const int rest = idx & 1023;
    const int bxt = rest & 31;               // n tile
    const int byt = rest >> 5;               // k tile
    const float* __restrict__ W = z ? wk : wq;
    const int tx = tid & 31, ty = tid >> 5;  // 32 x 8
    const int n = bxt * 32 + tx;
    const int k0 = byt * 32;
    #pragma unroll
    for (int i = 0; i < 4; i++)
        tile[ty + i * 8][tx] = W[(size_t)(k0 + ty + i * 8) * 1024 + n];
    __syncthreads();
    const int k = k0 + tx;
    const int nb = bxt * 32;
    #pragma unroll
    for (int i = 0; i < 4; i++) {
        const int nrow = nb + ty + i * 8;
        g_B[(size_t)(z * 1024 + nrow) * 1024 + k] =
            __float2bfloat16(tile[tx][ty + i * 8]);
    }
}

// ---------------- mma.sync GEMM ----------------
// CTA: 128x128 tile, 256 threads = 8 warps in 2(M) x 4(N); warp tile 64x32.
// K pipeline: BK=64 per stage, 4 stages, cp.async, single barrier per iter.
#define BK 64
#define STAGE_BYTES 32768   // (128 rows A + 128 rows B) * 128 bytes
#define NSTAGE 4

__global__ __launch_bounds__(256, 1)
void qk_mma_sync(const int* __restrict__ mask,
                 const float* __restrict__ bq,
                 const float* __restrict__ bk) {
    extern __shared__ __align__(1024) char smem[];
    const uint32_t base = smem_u32(smem);
    const int tid = threadIdx.x;
    const int warp = tid >> 5, lane = tid & 31;
    const int mBase = blockIdx.y * 128;
    const int nBase = blockIdx.x * 128;
    const int mw = (warp & 1) * 64;
    const int nw = (warp >> 1) * 32;

    float c[4][4][4];
    #pragma unroll
    for (int i = 0; i < 4; i++)
        #pragma unroll
        for (int j = 0; j < 4; j++)
            #pragma unroll
            for (int r = 0; r < 4; r++) c[i][j][r] = 0.f;

    auto issue = [&](int kb) {
        const int stage = kb & (NSTAGE - 1);
        const uint32_t sA = base + (uint32_t)stage * STAGE_BYTES;
        const uint32_t sB = sA + 16384;
        const int k0 = kb * BK;
        #pragma unroll
        for (int i = 0; i < 4; i++) {
            const int idx = i * 256 + tid;          // 0..1023
            const int row = idx >> 3;               // 0..127
            const int ch = idx & 7;                 // 16B chunk in row
            const uint32_t swz = (uint32_t)((ch ^ (row & 7)) << 4);
            const __nv_bfloat16* gA =
                g_A + (size_t)(mBase + row) * 1024 + k0 + ch * 8;
            const __nv_bfloat16* gB =
                g_B + (size_t)(nBase + row) * 1024 + k0 + ch * 8;
            asm volatile("cp.async.cg.shared.global [%0], [%1], 16;"
                         :: "r"(sA + (uint32_t)row * 128 + swz), "l"(gA));
            asm volatile("cp.async.cg.shared.global [%0], [%1], 16;"
                         :: "r"(sB + (uint32_t)row * 128 + swz), "l"(gB));
        }
        asm volatile("cp.async.commit_group;");
    };

    const int lj = lane >> 3;
    const int li = lane & 7;
    auto compute = [&](int stage) {
        const uint32_t sA = base + (uint32_t)stage * STAGE_BYTES;
        const uint32_t sB = sA + 16384;
        #pragma unroll
        for (int kc = 0; kc < BK / 16; kc++) {
            uint32_t a[4][4];
            #pragma unroll
            for (int mt = 0; mt < 4; mt++) {
                const int row = mw + mt * 16 + ((lj & 1) << 3) + li;
                const int ch = kc * 2 + (lj >> 1);
                const uint32_t addr =
                    sA + (uint32_t)row * 128 + (uint32_t)((ch ^ (row & 7)) << 4);
                asm volatile("ldmatrix.sync.aligned.m8n8.x4.shared.b16 "
                             "{%0,%1,%2,%3}, [%4];"
                             : "=r"(a[mt][0]), "=r"(a[mt][1]),
                               "=r"(a[mt][2]), "=r"(a[mt][3])
                             : "r"(addr));
            }
            uint32_t b[2][4];
            #pragma unroll
            for (int nh = 0; nh < 2; nh++) {
                const int row = nw + nh * 16 + ((lj >> 1) << 3) + li;
                const int ch = kc * 2 + (lj & 1);
                const uint32_t addr =
                    sB + (uint32_t)row * 128 + (uint32_t)((ch ^ (row & 7)) << 4);
                asm volatile("ldmatrix.sync.aligned.m8n8.x4.shared.b16 "
                             "{%0,%1,%2,%3}, [%4];"
                             : "=r"(b[nh][0]), "=r"(b[nh][1]),
                               "=r"(b[nh][2]), "=r"(b[nh][3])
                             : "r"(addr));
            }
            #pragma unroll
            for (int mt = 0; mt < 4; mt++)
                #pragma unroll
                for (int nt = 0; nt < 4; nt++) {
                    const uint32_t b0 = b[nt >> 1][(nt & 1) * 2 + 0];
                    const uint32_t b1 = b[nt >> 1][(nt & 1) * 2 + 1];
                    asm volatile(
                        "mma.sync.aligned.m16n8k16.row.col.f32.bf16.bf16.f32 "
                        "{%0,%1,%2,%3}, {%4,%5,%6,%7}, {%8,%9}, {%0,%1,%2,%3};"
                        : "+f"(c[mt][nt][0]), "+f"(c[mt][nt][1]),
                          "+f"(c[mt][nt][2]), "+f"(c[mt][nt][3])
                        : "r"(a[mt][0]), "r"(a[mt][1]),
                          "r"(a[mt][2]), "r"(a[mt][3]),
                          "r"(b0), "r"(b1));
                }
        }
    };

    // pipeline: 3 chunks in flight, 4 stages, one barrier per iteration
    issue(0); issue(1); issue(2);
    for (int kb = 0; kb < 16; kb++) {
        if (kb <= 13)      asm volatile("cp.async.wait_group 2;");
        else if (kb == 14) asm volatile("cp.async.wait_group 1;");
        else               asm volatile("cp.async.wait_group 0;");
        __syncthreads();
        if (kb + 3 < 16) issue(kb + 3);   // writes stage (kb-1)&3: free after sync
        compute(kb & (NSTAGE - 1));
    }

    // epilogue: bias + mask -> g_qk (f32)
    #pragma unroll
    for (int mt = 0; mt < 4; mt++) {
        #pragma unroll
        for (int half = 0; half < 2; half++) {
            const int row = mBase + mw + mt * 16 + (lane >> 2) + half * 8;
            const float m = (float)mask[row];
            #pragma unroll
            for (int nt = 0; nt < 4; nt++) {
                const int col = nBase + nw + nt * 8 + (lane & 3) * 2;
                const float bias0 = (col < 1024) ? bq[col] : bk[col - 1024];
                const float bias1 = (col + 1 < 1024) ? bq[col + 1] : bk[col + 1 - 1024];
                float2 v;
                v.x = (c[mt][nt][half * 2 + 0] + bias0) * m;
                v.y = (c[mt][nt][half * 2 + 1] + bias1) * m;
                *reinterpret_cast<float2*>(g_qk + (size_t)row * 2048 + col) = v;
            }
        }
    }
}

// ---------------- epi1: partial logits per (batch, dim-slice) ----------------
// grid (8, 32): blockIdx.x = slice (128 dims), blockIdx.y = batch. 256 threads.
__global__ __launch_bounds__(256) void epi1(float* __restrict__ dummy) {
    const int ds = blockIdx.x;           // 0..7
    const int b  = blockIdx.y;           // 0..31
    const int tid = threadIdx.x, warp = tid >> 5, lane = tid & 31;
    __shared__ float ks[128];

    const float* __restrict__ base = g_qk + (size_t)b * 32 * 2048;
    const int d0 = ds * 128;

    if (tid < 128) {
        float s = 0.f;
        #pragma unroll
        for (int a = 0; a < 32; a++)
            s += base[a * 2048 + 1024 + d0 + tid];
        ks[tid] = s;
    }
    __syncthreads();

    #pragma unroll
    for (int xi = 0; xi < 4; xi++) {
        const int x = warp + xi * 8;
        const float* __restrict__ q = base + (size_t)x * 2048 + d0;
        const float* __restrict__ k = q + 1024;
        const int d = lane * 4;
        const float4 qv = *reinterpret_cast<const float4*>(q + d);
        const float4 kv = *reinterpret_cast<const float4*>(k + d);
        const float4 sv = *reinterpret_cast<const float4*>(ks + d);
        float acc = qv.x * (sv.x - kv.x);
        acc = fmaf(qv.y, sv.y - kv.y, acc);
        acc = fmaf(qv.z, sv.z - kv.z, acc);
        acc = fmaf(qv.w, sv.w - kv.w, acc);
        #pragma unroll
        for (int o = 16; o > 0; o >>= 1)
            acc += __shfl_xor_sync(0xFFFFFFFFu, acc, o);
        if (lane == 0)
            g_part[(b * 32 + x) * 8 + ds] = acc;
    }
}

// ---------------- epi2: reduce slices + softmax ----------------
// 1 block, 1024 threads: warp = batch, lane = doc.
__global__ __launch_bounds__(1024) void epi2(const int* __restrict__ mask,
                                             float* __restrict__ out) {
    const int tid = threadIdx.x;
    const int lane = tid & 31;

    float s = 0.f;
    #pragma unroll
    for (int ds = 0; ds < 8; ds++)
        s += g_part[tid * 8 + ds];
    const float m = (float)mask[tid];
    float v = s + (1.0f - m) * -100000.0f;

    float mx = v;
    #pragma unroll
    for (int o = 16; o > 0; o >>= 1)
        mx = fmaxf(mx, __shfl_xor_sync(0xFFFFFFFFu, mx, o));
    float e = expf(v - mx);
    float sum = e;
    #pragma unroll
    for (int o = 16; o > 0; o >>= 1)
        sum += __shfl_xor_sync(0xFFFFFFFFu, sum, o);
    out[tid] = e / sum;
}

extern "C" void kernel_launch(void* const* d_in, const int* in_sizes, int n_in,
                              void* d_out, int out_size) {
    const float* enc  = (const float*)d_in[0];   // (32,32,128,1024) f32
    const int*   mask = (const int*)  d_in[1];   // (32,32) int32
    const float* wq   = (const float*)d_in[2];   // (1024,16,64) f32
    const float* bq   = (const float*)d_in[3];   // (16,64)
    const float* wk   = (const float*)d_in[4];
    const float* bk   = (const float*)d_in[5];
    float* out = (float*)d_out;                  // (32,32) f32

    cudaFuncSetAttribute(qk_mma_sync,
                         cudaFuncAttributeMaxDynamicSharedMemorySize,
                         NSTAGE * STAGE_BYTES);

    convert_all<<<3072, 256>>>(enc, wq, wk);
    qk_mma_sync<<<dim3(16, 8), 256, NSTAGE * STAGE_BYTES>>>(mask, bq, bk);
    epi1<<<dim3(8, 32), 256>>>(nullptr);
    epi2<<<1, 1024>>>(mask, out);
}